// round 4
// baseline (speedup 1.0000x reference)
#include <cuda_runtime.h>

#define BB 2
#define NF 16
#define HH 512
#define WW 512
#define H2 1024
#define W2 1024
#define CINc 50
#define HW (HH*WW)
#define HW2 (H2*W2)

#define TS 32              // output tile (512-res)
#define TW 66              // warped tile extent at 1024-res: 2*TS+2
#define TWN (TW*TW)        // 4356

// -------- scratch (device globals; referenced ONLY from device code) --------
__device__ float g_up16 [(size_t)BB*NF*HW2];   // upsampled tgt, planar
__device__ float g_warped[(size_t)BB*NF*HW];   // warped tgt @512, planar
__device__ float g_adj  [(size_t)BB*2*HW];     // conv output, planar
__device__ float g_newres[(size_t)BB*2*HW];    // combined residual, planar

// -------- resize helpers (jax.image.resize bilinear semantics; validated R1) ----
__device__ __forceinline__ void up_taps(int i, int n_in, int& t0, int& t1,
                                        float& w0, float& w1) {
    int k = i >> 1;
    if ((i & 1) == 0) { t0 = k - 1; t1 = k;     w0 = 0.25f; w1 = 0.75f; }
    else              { t0 = k;     t1 = k + 1; w0 = 0.75f; w1 = 0.25f; }
    if (t0 < 0)     { t0 = t1; w0 = 0.f; w1 = 1.f; }
    if (t1 >= n_in) { t1 = t0; w1 = 0.f; w0 = 1.f; }
}
__device__ __forceinline__ float dbase(int t) { return (t == 0 || t == 3) ? 0.25f : 0.75f; }

// on-the-fly upsample of a 2-channel 512 field at 1024 coords, *2 (flow scaling)
__device__ __forceinline__ float2 up_field(const float* __restrict__ f0,
                                           const float* __restrict__ f1,
                                           int Y, int X) {
    Y = min(max(Y, 0), H2 - 1);
    X = min(max(X, 0), W2 - 1);
    int ty0, ty1, tx0, tx1; float wy0, wy1, wx0, wx1;
    up_taps(Y, HH, ty0, ty1, wy0, wy1);
    up_taps(X, WW, tx0, tx1, wx0, wx1);
    int r0 = ty0 * WW, r1 = ty1 * WW;
    float vx = wy0 * (wx0 * f0[r0 + tx0] + wx1 * f0[r0 + tx1])
             + wy1 * (wx0 * f0[r1 + tx0] + wx1 * f0[r1 + tx1]);
    float vy = wy0 * (wx0 * f1[r0 + tx0] + wx1 * f1[r0 + tx1])
             + wy1 * (wx0 * f1[r1 + tx0] + wx1 * f1[r1 + tx1]);
    return make_float2(2.f * vx, 2.f * vy);
}

__device__ __forceinline__ void gather_setup(float sx, float sy,
        int& o00, int& o01, int& o10, int& o11,
        float& w00, float& w01, float& w10, float& w11) {
    float xf = floorf(sx), yf = floorf(sy);
    float fx = sx - xf, fy = sy - yf;
    int ix0 = (int)xf, iy0 = (int)yf;
    int ix1 = ix0 + 1, iy1 = iy0 + 1;
    w00 = (1.f - fy) * (1.f - fx); w01 = (1.f - fy) * fx;
    w10 = fy * (1.f - fx);         w11 = fy * fx;
    bool bx0 = (unsigned)ix0 < W2, bx1 = (unsigned)ix1 < W2;
    bool by0 = (unsigned)iy0 < H2, by1 = (unsigned)iy1 < H2;
    if (!(by0 && bx0)) w00 = 0.f;
    if (!(by0 && bx1)) w01 = 0.f;
    if (!(by1 && bx0)) w10 = 0.f;
    if (!(by1 && bx1)) w11 = 0.f;
    int cx0 = min(max(ix0, 0), W2 - 1), cx1 = min(max(ix1, 0), W2 - 1);
    int cy0 = min(max(iy0, 0), H2 - 1), cy1 = min(max(iy1, 0), H2 - 1);
    o00 = cy0 * W2 + cx0; o01 = cy0 * W2 + cx1;
    o10 = cy1 * W2 + cx0; o11 = cy1 * W2 + cx1;
}

// -------- kernel 1: upsample tgt 512->1024, 4 outputs/thread, float4 store ------
__global__ void k_up_img(const float* __restrict__ x) {
    int idx = blockIdx.x * blockDim.x + threadIdx.x;
    if (idx >= BB * H2 * (W2 / 4)) return;
    int xq = idx & (W2 / 4 - 1);             // quad index: cols 4*xq .. 4*xq+3
    int yy = (idx >> 8) & (H2 - 1);
    int b  = idx >> 18;
    int m = 2 * xq;                          // cols {4xq..4xq+3} need src cols m-1..m+2
    int mm1 = max(m - 1, 0), mp2 = min(m + 2, WW - 1);
    // per-output x-weights (2 taps each), with edge renorm
    float a00 = (m == 0) ? 0.f : 0.25f,  a01 = (m == 0) ? 1.f : 0.75f;   // col 2m : F[mm1],F[m]
    float a30 = (m == WW - 2) ? 1.f : 0.75f, a31 = (m == WW - 2) ? 0.f : 0.25f; // col 2m+3: F[m+1],F[mp2]
    int ty0, ty1; float wy0, wy1;
    up_taps(yy, HH, ty0, ty1, wy0, wy1);
    int r0 = ty0 * WW, r1 = ty1 * WW;

    const float* xb = x + ((size_t)b * 2 * NF + NF) * HW;
    float* ob = g_up16 + (size_t)b * NF * HW2 + (size_t)yy * W2 + 4 * xq;
    #pragma unroll
    for (int c = 0; c < NF; c++) {
        const float* p = xb + (size_t)c * HW;
        float u0 = p[r0 + mm1], u1 = p[r0 + m], u2 = p[r0 + m + 1], u3 = p[r0 + mp2];
        float v0 = p[r1 + mm1], v1 = p[r1 + m], v2 = p[r1 + m + 1], v3 = p[r1 + mp2];
        float s0 = u0 * wy0 + v0 * wy1;
        float s1 = u1 * wy0 + v1 * wy1;
        float s2 = u2 * wy0 + v2 * wy1;
        float s3 = u3 * wy0 + v3 * wy1;
        float4 o;
        o.x = a00 * s0 + a01 * s1;          // col 2m   (even)
        o.y = 0.75f * s1 + 0.25f * s2;      // col 2m+1 (odd)
        o.z = 0.25f * s1 + 0.75f * s2;      // col 2m+2 (even)
        o.w = a30 * s2 + a31 * s3;          // col 2m+3 (odd)
        *(float4*)(ob + (size_t)c * HW2) = o;
    }
}

// -------- fused: field-up (once) -> gather tables -> 16ch warp+downsample -------
// field_sel: 0 = ext_field (res input), 1 = g_newres
// to_final : 0 -> g_warped ; 1 -> out channels 16..31 of 32
__global__ void k_warpdown(const float* __restrict__ ext_field, int field_sel,
                           float* __restrict__ out, int to_final) {
    extern __shared__ float sh[];
    float4*   s_w4 = (float4*)sh;                     // [TWN] masked corner weights
    unsigned* s_pk = (unsigned*)(sh + 4 * TWN);       // [TWN] packed offset|dx|dy
    float*    s_w  = sh + 5 * TWN;                    // [TWN] warped plane (per ch)
    int b = blockIdx.z;
    int x0 = blockIdx.x * TS, y0 = blockIdx.y * TS;
    int gx0 = 2 * x0 - 1, gy0 = 2 * y0 - 1;
    int tid = threadIdx.x;

    const float* fbase = (field_sel == 0) ? ext_field : g_newres;
    const float* f0 = fbase + (size_t)b * 2 * HW;
    const float* f1 = f0 + HW;

    // ---- setup pass: gather geometry once per pixel ----
    for (int i = tid; i < TWN; i += 256) {
        int r = i / TW, cc = i - r * TW;
        float2 f = up_field(f0, f1, gy0 + r, gx0 + cc);
        float sx = (float)(gx0 + cc) + f.x;
        float sy = (float)(gy0 + r) + f.y;
        float xf = floorf(sx), yf = floorf(sy);
        float fx = sx - xf, fy = sy - yf;
        int ix0 = (int)xf, iy0 = (int)yf;
        bool bx0 = (unsigned)ix0 < W2, bx1 = (unsigned)(ix0 + 1) < W2;
        bool by0 = (unsigned)iy0 < H2, by1 = (unsigned)(iy0 + 1) < H2;
        float wx0 = bx0 ? (1.f - fx) : 0.f, wx1 = bx1 ? fx : 0.f;
        float wy0 = by0 ? (1.f - fy) : 0.f, wy1 = by1 ? fy : 0.f;
        s_w4[i] = make_float4(wy0 * wx0, wy0 * wx1, wy1 * wx0, wy1 * wx1);
        int cx0 = min(max(ix0, 0), W2 - 1), cx1 = min(max(ix0 + 1, 0), W2 - 1);
        int cy0 = min(max(iy0, 0), H2 - 1), cy1 = min(max(iy0 + 1, 0), H2 - 1);
        s_pk[i] = (unsigned)(cy0 * W2 + cx0)
                | ((unsigned)(cx1 - cx0) << 20)
                | ((unsigned)(cy1 - cy0) << 21);
    }
    __syncthreads();

    const float* img = g_up16 + (size_t)b * NF * HW2;
    float* dstb = to_final ? (out + ((size_t)b * 2 * NF + NF) * HW)
                           : (g_warped + (size_t)b * NF * HW);
    int lx = tid & 31, ly0 = tid >> 5;

    for (int c = 0; c < NF; c++) {
        const float* p = img + (size_t)c * HW2;
        for (int i = tid; i < TWN; i += 256) {
            unsigned pk = s_pk[i];
            float4 w = s_w4[i];
            int o00 = (int)(pk & 0xFFFFFu);
            int dx  = (int)((pk >> 20) & 1u);
            int o10 = o00 + (int)((pk >> 11) & 1024u);   // + dy*W2
            int o01 = o00 + dx;
            int o11 = o10 + dx;
            s_w[i] = w.x * p[o00] + w.y * p[o01] + w.z * p[o10] + w.w * p[o11];
        }
        __syncthreads();
        float* op = dstb + (size_t)c * HW;
        #pragma unroll
        for (int k = 0; k < 4; k++) {
            int ly = ly0 + 8 * k;
            int yy = y0 + ly, xx = x0 + lx;
            float invsy = (yy == 0 || yy == HH - 1) ? (1.f / 1.75f) : 0.5f;
            float invsx = (xx == 0 || xx == WW - 1) ? (1.f / 1.75f) : 0.5f;
            float acc = 0.f;
            #pragma unroll
            for (int ty = 0; ty < 4; ty++) {
                int GY = gy0 + 2 * ly + ty;
                if ((unsigned)GY >= H2) continue;
                float wy = dbase(ty) * invsy;
                int sr = (2 * ly + ty) * TW + 2 * lx;
                #pragma unroll
                for (int tx = 0; tx < 4; tx++) {
                    int GX = gx0 + 2 * lx + tx;
                    if ((unsigned)GX >= W2) continue;
                    acc += wy * dbase(tx) * invsx * s_w[sr + tx];
                }
            }
            op[yy * WW + xx] = acc;
        }
        __syncthreads();
    }
}

// -------- 3x3 conv 50->2, plus pass-through of src channels to out --------
__global__ void k_conv(const float* __restrict__ x, const float* __restrict__ res,
                       const float* __restrict__ Wc, const float* __restrict__ bias,
                       float* __restrict__ out) {
    __shared__ float sw[2 * CINc * 9];
    for (int i = threadIdx.x; i < 2 * CINc * 9; i += blockDim.x) sw[i] = Wc[i];
    __syncthreads();
    int idx = blockIdx.x * blockDim.x + threadIdx.x;
    if (idx >= BB * HW) return;
    int xx = idx & (WW - 1), yy = (idx >> 9) & (HH - 1), b = idx >> 18;
    float a0 = bias[0], a1 = bias[1];
    const float* xb = x + (size_t)b * 2 * NF * HW;
    const float* wb = g_warped + (size_t)b * NF * HW;
    const float* rb = res + (size_t)b * 2 * HW;
    for (int dy = -1; dy <= 1; dy++) {
        int y2 = yy + dy;
        if ((unsigned)y2 >= HH) continue;
        for (int dx = -1; dx <= 1; dx++) {
            int x2 = xx + dx;
            if ((unsigned)x2 >= WW) continue;
            int kidx = (dy + 1) * 3 + (dx + 1);
            int p = y2 * WW + x2;
            const float* s0 = sw + kidx;
            const float* s1 = sw + CINc * 9 + kidx;
            #pragma unroll 8
            for (int c = 0; c < 32; c++) {
                float v = xb[(size_t)c * HW + p];
                a0 += v * s0[c * 9];
                a1 += v * s1[c * 9];
            }
            #pragma unroll 8
            for (int c = 0; c < 16; c++) {
                float v = wb[(size_t)c * HW + p];
                a0 += v * s0[(32 + c) * 9];
                a1 += v * s1[(32 + c) * 9];
            }
            float v0 = rb[p], v1 = rb[HW + p];
            a0 += v0 * s0[48 * 9] + v1 * s0[49 * 9];
            a1 += v0 * s1[48 * 9] + v1 * s1[49 * 9];
        }
    }
    int pc = yy * WW + xx;
    float* o = g_adj + (size_t)b * 2 * HW + pc;
    o[0] = a0;
    o[HW] = a1;
    float* ob = out + (size_t)b * 2 * NF * HW + pc;
    #pragma unroll
    for (int c = 0; c < NF; c++) ob[(size_t)c * HW] = xb[(size_t)c * HW + pc];
}

// -------- fused: warp res-field(up) by adj-field(up) -> downsample*0.5 + adj ------
__global__ void k_combine_f(const float* __restrict__ res) {
    extern __shared__ float sh[];
    float2* s_f = (float2*)sh;          // [TWN] b-field (upsampled adj*2)
    float2* s_w = s_f + TWN;            // [TWN] warped a-field values
    int b = blockIdx.z;
    int x0 = blockIdx.x * TS, y0 = blockIdx.y * TS;
    int gx0 = 2 * x0 - 1, gy0 = 2 * y0 - 1;
    int tid = threadIdx.x;

    const float* a0 = res + (size_t)b * 2 * HW;
    const float* a1 = a0 + HW;
    const float* bf0 = g_adj + (size_t)b * 2 * HW;
    const float* bf1 = bf0 + HW;

    for (int i = tid; i < TWN; i += 256) {
        int r = i / TW, cc = i - r * TW;
        s_f[i] = up_field(bf0, bf1, gy0 + r, gx0 + cc);
    }
    __syncthreads();

    for (int i = tid; i < TWN; i += 256) {
        int r = i / TW, cc = i - r * TW;
        float2 f = s_f[i];
        float sx = (float)(gx0 + cc) + f.x;
        float sy = (float)(gy0 + r) + f.y;
        int o00, o01, o10, o11; float w00, w01, w10, w11;
        gather_setup(sx, sy, o00, o01, o10, o11, w00, w01, w10, w11);
        float ax = 0.f, ay = 0.f;
        if (w00 != 0.f) { float2 v = up_field(a0, a1, o00 >> 10, o00 & (W2 - 1)); ax += w00 * v.x; ay += w00 * v.y; }
        if (w01 != 0.f) { float2 v = up_field(a0, a1, o01 >> 10, o01 & (W2 - 1)); ax += w01 * v.x; ay += w01 * v.y; }
        if (w10 != 0.f) { float2 v = up_field(a0, a1, o10 >> 10, o10 & (W2 - 1)); ax += w10 * v.x; ay += w10 * v.y; }
        if (w11 != 0.f) { float2 v = up_field(a0, a1, o11 >> 10, o11 & (W2 - 1)); ax += w11 * v.x; ay += w11 * v.y; }
        s_w[i] = make_float2(ax, ay);
    }
    __syncthreads();

    int lx = tid & 31, ly0 = tid >> 5;
    #pragma unroll
    for (int k = 0; k < 4; k++) {
        int ly = ly0 + 8 * k;
        int yy = y0 + ly, xx = x0 + lx;
        float invsy = (yy == 0 || yy == HH - 1) ? (1.f / 1.75f) : 0.5f;
        float invsx = (xx == 0 || xx == WW - 1) ? (1.f / 1.75f) : 0.5f;
        float accx = 0.f, accy = 0.f;
        #pragma unroll
        for (int ty = 0; ty < 4; ty++) {
            int GY = gy0 + 2 * ly + ty;
            if ((unsigned)GY >= H2) continue;
            float wy = dbase(ty) * invsy;
            int sr = (2 * ly + ty) * TW + 2 * lx;
            #pragma unroll
            for (int tx = 0; tx < 4; tx++) {
                int GX = gx0 + 2 * lx + tx;
                if ((unsigned)GX >= W2) continue;
                float w = wy * dbase(tx) * invsx;
                float2 v = s_w[sr + tx];
                accx += w * v.x;
                accy += w * v.y;
            }
        }
        int p = yy * WW + xx;
        const float* ad = g_adj + (size_t)b * 2 * HW;
        float* nr = g_newres + (size_t)b * 2 * HW;
        nr[p]      = ad[p]      + 0.5f * accx;
        nr[HW + p] = ad[HW + p] + 0.5f * accy;
    }
}

// -------- launch --------
extern "C" void kernel_launch(void* const* d_in, const int* in_sizes, int n_in,
                              void* d_out, int out_size) {
    const float* x    = (const float*)d_in[0];
    const float* res  = (const float*)d_in[1];
    const float* Wc   = (const float*)d_in[2];
    const float* bias = (const float*)d_in[3];
    float* out = (float*)d_out;

    const int T = 256;
    const int n_up  = BB * H2 * (W2 / 4);
    const int n512  = BB * HW;
    dim3 gu((n_up + T - 1) / T);
    dim3 g2((n512 + T - 1) / T);
    dim3 gt(HH / TS, WW / TS, BB);   // 16 x 16 x 2 tile grid

    const int smem_wd = (6 * TWN) * (int)sizeof(float);   // 104,544 B
    const int smem_cb = (4 * TWN) * (int)sizeof(float);   //  69,696 B
    static bool attr_set = false;
    if (!attr_set) {
        cudaFuncSetAttribute(k_warpdown, cudaFuncAttributeMaxDynamicSharedMemorySize, smem_wd);
        cudaFuncSetAttribute(k_combine_f, cudaFuncAttributeMaxDynamicSharedMemorySize, smem_cb);
        attr_set = true;
    }

    k_up_img<<<gu, T>>>(x);                                  // tgt -> g_up16
    k_warpdown<<<gt, T, smem_wd>>>(res, 0, nullptr, 0);      // warp by res -> g_warped
    k_conv<<<g2, T>>>(x, res, Wc, bias, out);                // adj + src pass-through
    k_combine_f<<<gt, T, smem_cb>>>(res);                    // -> g_newres
    k_warpdown<<<gt, T, smem_wd>>>(nullptr, 1, out, 1);      // warp by new_res -> out[16..31]
}

// round 5
// speedup vs baseline: 1.8598x; 1.8598x over previous
#include <cuda_runtime.h>

#define BB 2
#define NF 16
#define HH 512
#define WW 512
#define H2 1024
#define W2 1024
#define CINc 50
#define HW (HH*WW)
#define HW2 (H2*W2)

// warpdown tiles (16x16 outputs)
#define TSW 16
#define TWW 34             // 2*TSW+2
#define TWNW (TWW*TWW)     // 1156
// combine tiles (32x32 outputs)
#define TS 32
#define TW 66
#define TWN (TW*TW)        // 4356

// -------- scratch (device globals; referenced ONLY from device code) --------
__device__ float g_up16 [(size_t)BB*NF*HW2];   // upsampled tgt, planar
__device__ float g_warped[(size_t)BB*NF*HW];   // warped tgt @512, planar
__device__ float g_adj  [(size_t)BB*2*HW];     // conv output, planar
__device__ float g_newres[(size_t)BB*2*HW];    // combined residual, planar

// -------- resize helpers (jax.image.resize bilinear semantics; validated R1) ----
__device__ __forceinline__ void up_taps(int i, int n_in, int& t0, int& t1,
                                        float& w0, float& w1) {
    int k = i >> 1;
    if ((i & 1) == 0) { t0 = k - 1; t1 = k;     w0 = 0.25f; w1 = 0.75f; }
    else              { t0 = k;     t1 = k + 1; w0 = 0.75f; w1 = 0.25f; }
    if (t0 < 0)     { t0 = t1; w0 = 0.f; w1 = 1.f; }
    if (t1 >= n_in) { t1 = t0; w1 = 0.f; w0 = 1.f; }
}
__device__ __forceinline__ float dbase(int t) { return (t == 0 || t == 3) ? 0.25f : 0.75f; }

// on-the-fly upsample of a 2-channel 512 field at 1024 coords, *2 (flow scaling)
__device__ __forceinline__ float2 up_field(const float* __restrict__ f0,
                                           const float* __restrict__ f1,
                                           int Y, int X) {
    Y = min(max(Y, 0), H2 - 1);
    X = min(max(X, 0), W2 - 1);
    int ty0, ty1, tx0, tx1; float wy0, wy1, wx0, wx1;
    up_taps(Y, HH, ty0, ty1, wy0, wy1);
    up_taps(X, WW, tx0, tx1, wx0, wx1);
    int r0 = ty0 * WW, r1 = ty1 * WW;
    float vx = wy0 * (wx0 * f0[r0 + tx0] + wx1 * f0[r0 + tx1])
             + wy1 * (wx0 * f0[r1 + tx0] + wx1 * f0[r1 + tx1]);
    float vy = wy0 * (wx0 * f1[r0 + tx0] + wx1 * f1[r0 + tx1])
             + wy1 * (wx0 * f1[r1 + tx0] + wx1 * f1[r1 + tx1]);
    return make_float2(2.f * vx, 2.f * vy);
}

__device__ __forceinline__ void gather_setup(float sx, float sy,
        int& o00, int& o01, int& o10, int& o11,
        float& w00, float& w01, float& w10, float& w11) {
    float xf = floorf(sx), yf = floorf(sy);
    float fx = sx - xf, fy = sy - yf;
    int ix0 = (int)xf, iy0 = (int)yf;
    int ix1 = ix0 + 1, iy1 = iy0 + 1;
    w00 = (1.f - fy) * (1.f - fx); w01 = (1.f - fy) * fx;
    w10 = fy * (1.f - fx);         w11 = fy * fx;
    bool bx0 = (unsigned)ix0 < W2, bx1 = (unsigned)ix1 < W2;
    bool by0 = (unsigned)iy0 < H2, by1 = (unsigned)iy1 < H2;
    if (!(by0 && bx0)) w00 = 0.f;
    if (!(by0 && bx1)) w01 = 0.f;
    if (!(by1 && bx0)) w10 = 0.f;
    if (!(by1 && bx1)) w11 = 0.f;
    int cx0 = min(max(ix0, 0), W2 - 1), cx1 = min(max(ix1, 0), W2 - 1);
    int cy0 = min(max(iy0, 0), H2 - 1), cy1 = min(max(iy1, 0), H2 - 1);
    o00 = cy0 * W2 + cx0; o01 = cy0 * W2 + cx1;
    o10 = cy1 * W2 + cx0; o11 = cy1 * W2 + cx1;
}

// -------- kernel 1: upsample tgt 512->1024, 4 outputs/thread, float4 store ------
__global__ void __launch_bounds__(256) k_up_img(const float* __restrict__ x) {
    int idx = blockIdx.x * blockDim.x + threadIdx.x;
    if (idx >= BB * H2 * (W2 / 4)) return;
    int xq = idx & (W2 / 4 - 1);
    int yy = (idx >> 8) & (H2 - 1);
    int b  = idx >> 18;
    int m = 2 * xq;
    int mm1 = max(m - 1, 0), mp2 = min(m + 2, WW - 1);
    float a00 = (m == 0) ? 0.f : 0.25f,  a01 = (m == 0) ? 1.f : 0.75f;
    float a30 = (m == WW - 2) ? 1.f : 0.75f, a31 = (m == WW - 2) ? 0.f : 0.25f;
    int ty0, ty1; float wy0, wy1;
    up_taps(yy, HH, ty0, ty1, wy0, wy1);
    int r0 = ty0 * WW, r1 = ty1 * WW;

    const float* xb = x + ((size_t)b * 2 * NF + NF) * HW;
    float* ob = g_up16 + (size_t)b * NF * HW2 + (size_t)yy * W2 + 4 * xq;
    #pragma unroll
    for (int c = 0; c < NF; c++) {
        const float* p = xb + (size_t)c * HW;
        float u0 = p[r0 + mm1], u1 = p[r0 + m], u2 = p[r0 + m + 1], u3 = p[r0 + mp2];
        float v0 = p[r1 + mm1], v1 = p[r1 + m], v2 = p[r1 + m + 1], v3 = p[r1 + mp2];
        float s0 = u0 * wy0 + v0 * wy1;
        float s1 = u1 * wy0 + v1 * wy1;
        float s2 = u2 * wy0 + v2 * wy1;
        float s3 = u3 * wy0 + v3 * wy1;
        float4 o;
        o.x = a00 * s0 + a01 * s1;
        o.y = 0.75f * s1 + 0.25f * s2;
        o.z = 0.25f * s1 + 0.75f * s2;
        o.w = a30 * s2 + a31 * s3;
        *(float4*)(ob + (size_t)c * HW2) = o;
    }
}

// -------- fused: field-up + gather tables (once) -> 16ch warp+downsample --------
// field_sel: 0 = ext_field (res input), 1 = g_newres
// to_final : 0 -> g_warped ; 1 -> out channels 16..31 of 32
__global__ void __launch_bounds__(256) k_warpdown(
        const float* __restrict__ ext_field, int field_sel,
        float* __restrict__ out, int to_final) {
    __shared__ float4   s_w4[TWNW];     // masked corner weights
    __shared__ unsigned s_pk[TWNW];     // packed offset | dx<<20 | dy<<21
    __shared__ float    s_w [TWNW];     // warped plane (per channel)
    int b = blockIdx.z;
    int x0 = blockIdx.x * TSW, y0 = blockIdx.y * TSW;
    int gx0 = 2 * x0 - 1, gy0 = 2 * y0 - 1;
    int tid = threadIdx.x;

    const float* fbase = (field_sel == 0) ? ext_field : g_newres;
    const float* f0 = fbase + (size_t)b * 2 * HW;
    const float* f1 = f0 + HW;

    // ---- setup: gather geometry once per 1024-pos ----
    for (int i = tid; i < TWNW; i += 256) {
        int r = i / TWW, cc = i - r * TWW;
        float2 f = up_field(f0, f1, gy0 + r, gx0 + cc);
        float sx = (float)(gx0 + cc) + f.x;
        float sy = (float)(gy0 + r) + f.y;
        float xf = floorf(sx), yf = floorf(sy);
        float fx = sx - xf, fy = sy - yf;
        int ix0 = (int)xf, iy0 = (int)yf;
        bool bx0 = (unsigned)ix0 < W2, bx1 = (unsigned)(ix0 + 1) < W2;
        bool by0 = (unsigned)iy0 < H2, by1 = (unsigned)(iy0 + 1) < H2;
        float wx0 = bx0 ? (1.f - fx) : 0.f, wx1 = bx1 ? fx : 0.f;
        float wy0 = by0 ? (1.f - fy) : 0.f, wy1 = by1 ? fy : 0.f;
        s_w4[i] = make_float4(wy0 * wx0, wy0 * wx1, wy1 * wx0, wy1 * wx1);
        int cx0 = min(max(ix0, 0), W2 - 1), cx1 = min(max(ix0 + 1, 0), W2 - 1);
        int cy0 = min(max(iy0, 0), H2 - 1), cy1 = min(max(iy0 + 1, 0), H2 - 1);
        s_pk[i] = (unsigned)(cy0 * W2 + cx0)
                | ((unsigned)(cx1 - cx0) << 20)
                | ((unsigned)(cy1 - cy0) << 21);
    }
    __syncthreads();

    const float* img = g_up16 + (size_t)b * NF * HW2;
    float* dstb = to_final ? (out + ((size_t)b * 2 * NF + NF) * HW)
                           : (g_warped + (size_t)b * NF * HW);
    int lx = tid & (TSW - 1), ly = tid >> 4;   // one output pixel per thread
    int yy = y0 + ly, xx = x0 + lx;
    // downsample weights with bounds folded in (zero weight for OOR taps)
    float invsy = (yy == 0 || yy == HH - 1) ? (1.f / 1.75f) : 0.5f;
    float invsx = (xx == 0 || xx == WW - 1) ? (1.f / 1.75f) : 0.5f;
    float wyv[4], wxv[4];
    #pragma unroll
    for (int t = 0; t < 4; t++) {
        int GY = gy0 + 2 * ly + t;
        int GX = gx0 + 2 * lx + t;
        wyv[t] = ((unsigned)GY < H2) ? dbase(t) * invsy : 0.f;
        wxv[t] = ((unsigned)GX < W2) ? dbase(t) * invsx : 0.f;
    }
    int sbase = (2 * ly) * TWW + 2 * lx;

    for (int c = 0; c < NF; c++) {
        const float* p = img + (size_t)c * HW2;
        for (int i = tid; i < TWNW; i += 256) {
            unsigned pk = s_pk[i];
            float4 w = s_w4[i];
            int o00 = (int)(pk & 0xFFFFFu);
            int dx  = (int)((pk >> 20) & 1u);
            int o10 = o00 + (int)((pk >> 11) & 1024u);   // + dy*W2
            s_w[i] = w.x * p[o00] + w.y * p[o00 + dx] + w.z * p[o10] + w.w * p[o10 + dx];
        }
        __syncthreads();
        float acc = 0.f;
        #pragma unroll
        for (int ty = 0; ty < 4; ty++) {
            const float* sr = s_w + sbase + ty * TWW;
            float rowv = wxv[0] * sr[0] + wxv[1] * sr[1] + wxv[2] * sr[2] + wxv[3] * sr[3];
            acc += wyv[ty] * rowv;
        }
        dstb[(size_t)c * HW + yy * WW + xx] = acc;
        __syncthreads();
    }
}

// -------- 3x3 conv 50->2, plus pass-through of src channels to out --------
__global__ void __launch_bounds__(256) k_conv(
        const float* __restrict__ x, const float* __restrict__ res,
        const float* __restrict__ Wc, const float* __restrict__ bias,
        float* __restrict__ out) {
    __shared__ float sw[2 * CINc * 9];
    for (int i = threadIdx.x; i < 2 * CINc * 9; i += blockDim.x) sw[i] = Wc[i];
    __syncthreads();
    int idx = blockIdx.x * blockDim.x + threadIdx.x;
    if (idx >= BB * HW) return;
    int xx = idx & (WW - 1), yy = (idx >> 9) & (HH - 1), b = idx >> 18;
    float a0 = bias[0], a1 = bias[1];
    const float* xb = x + (size_t)b * 2 * NF * HW;
    const float* wb = g_warped + (size_t)b * NF * HW;
    const float* rb = res + (size_t)b * 2 * HW;
    for (int dy = -1; dy <= 1; dy++) {
        int y2 = yy + dy;
        if ((unsigned)y2 >= HH) continue;
        for (int dx = -1; dx <= 1; dx++) {
            int x2 = xx + dx;
            if ((unsigned)x2 >= WW) continue;
            int kidx = (dy + 1) * 3 + (dx + 1);
            int p = y2 * WW + x2;
            const float* s0 = sw + kidx;
            const float* s1 = sw + CINc * 9 + kidx;
            #pragma unroll 8
            for (int c = 0; c < 32; c++) {
                float v = xb[(size_t)c * HW + p];
                a0 += v * s0[c * 9];
                a1 += v * s1[c * 9];
            }
            #pragma unroll 8
            for (int c = 0; c < 16; c++) {
                float v = wb[(size_t)c * HW + p];
                a0 += v * s0[(32 + c) * 9];
                a1 += v * s1[(32 + c) * 9];
            }
            float v0 = rb[p], v1 = rb[HW + p];
            a0 += v0 * s0[48 * 9] + v1 * s0[49 * 9];
            a1 += v0 * s1[48 * 9] + v1 * s1[49 * 9];
        }
    }
    int pc = yy * WW + xx;
    float* o = g_adj + (size_t)b * 2 * HW + pc;
    o[0] = a0;
    o[HW] = a1;
    float* ob = out + (size_t)b * 2 * NF * HW + pc;
    #pragma unroll
    for (int c = 0; c < NF; c++) ob[(size_t)c * HW] = xb[(size_t)c * HW + pc];
}

// -------- fused: warp res-field(up) by adj-field(up) -> downsample*0.5 + adj ------
__global__ void __launch_bounds__(256) k_combine_f(const float* __restrict__ res) {
    extern __shared__ float sh[];
    float2* s_f = (float2*)sh;          // [TWN] b-field (upsampled adj*2)
    float2* s_w = s_f + TWN;            // [TWN] warped a-field values
    int b = blockIdx.z;
    int x0 = blockIdx.x * TS, y0 = blockIdx.y * TS;
    int gx0 = 2 * x0 - 1, gy0 = 2 * y0 - 1;
    int tid = threadIdx.x;

    const float* a0 = res + (size_t)b * 2 * HW;
    const float* a1 = a0 + HW;
    const float* bf0 = g_adj + (size_t)b * 2 * HW;
    const float* bf1 = bf0 + HW;

    for (int i = tid; i < TWN; i += 256) {
        int r = i / TW, cc = i - r * TW;
        s_f[i] = up_field(bf0, bf1, gy0 + r, gx0 + cc);
    }
    __syncthreads();

    for (int i = tid; i < TWN; i += 256) {
        int r = i / TW, cc = i - r * TW;
        float2 f = s_f[i];
        float sx = (float)(gx0 + cc) + f.x;
        float sy = (float)(gy0 + r) + f.y;
        int o00, o01, o10, o11; float w00, w01, w10, w11;
        gather_setup(sx, sy, o00, o01, o10, o11, w00, w01, w10, w11);
        float ax = 0.f, ay = 0.f;
        if (w00 != 0.f) { float2 v = up_field(a0, a1, o00 >> 10, o00 & (W2 - 1)); ax += w00 * v.x; ay += w00 * v.y; }
        if (w01 != 0.f) { float2 v = up_field(a0, a1, o01 >> 10, o01 & (W2 - 1)); ax += w01 * v.x; ay += w01 * v.y; }
        if (w10 != 0.f) { float2 v = up_field(a0, a1, o10 >> 10, o10 & (W2 - 1)); ax += w10 * v.x; ay += w10 * v.y; }
        if (w11 != 0.f) { float2 v = up_field(a0, a1, o11 >> 10, o11 & (W2 - 1)); ax += w11 * v.x; ay += w11 * v.y; }
        s_w[i] = make_float2(ax, ay);
    }
    __syncthreads();

    int lx = tid & 31, ly0 = tid >> 5;
    #pragma unroll
    for (int k = 0; k < 4; k++) {
        int ly = ly0 + 8 * k;
        int yy = y0 + ly, xx = x0 + lx;
        float invsy = (yy == 0 || yy == HH - 1) ? (1.f / 1.75f) : 0.5f;
        float invsx = (xx == 0 || xx == WW - 1) ? (1.f / 1.75f) : 0.5f;
        float accx = 0.f, accy = 0.f;
        #pragma unroll
        for (int ty = 0; ty < 4; ty++) {
            int GY = gy0 + 2 * ly + ty;
            if ((unsigned)GY >= H2) continue;
            float wy = dbase(ty) * invsy;
            int sr = (2 * ly + ty) * TW + 2 * lx;
            #pragma unroll
            for (int tx = 0; tx < 4; tx++) {
                int GX = gx0 + 2 * lx + tx;
                if ((unsigned)GX >= W2) continue;
                float w = wy * dbase(tx) * invsx;
                float2 v = s_w[sr + tx];
                accx += w * v.x;
                accy += w * v.y;
            }
        }
        int p = yy * WW + xx;
        const float* ad = g_adj + (size_t)b * 2 * HW;
        float* nr = g_newres + (size_t)b * 2 * HW;
        nr[p]      = ad[p]      + 0.5f * accx;
        nr[HW + p] = ad[HW + p] + 0.5f * accy;
    }
}

// -------- launch --------
extern "C" void kernel_launch(void* const* d_in, const int* in_sizes, int n_in,
                              void* d_out, int out_size) {
    const float* x    = (const float*)d_in[0];
    const float* res  = (const float*)d_in[1];
    const float* Wc   = (const float*)d_in[2];
    const float* bias = (const float*)d_in[3];
    float* out = (float*)d_out;

    const int T = 256;
    const int n_up  = BB * H2 * (W2 / 4);
    const int n512  = BB * HW;
    dim3 gu((n_up + T - 1) / T);
    dim3 g2((n512 + T - 1) / T);
    dim3 gw(HH / TSW, WW / TSW, BB);   // 32 x 32 x 2 warpdown tiles
    dim3 gc(HH / TS,  WW / TS,  BB);   // 16 x 16 x 2 combine tiles

    const int smem_cb = (4 * TWN) * (int)sizeof(float);   // 69,696 B
    static bool attr_set = false;
    if (!attr_set) {
        cudaFuncSetAttribute(k_combine_f, cudaFuncAttributeMaxDynamicSharedMemorySize, smem_cb);
        attr_set = true;
    }

    k_up_img<<<gu, T>>>(x);                               // tgt -> g_up16
    k_warpdown<<<gw, T>>>(res, 0, nullptr, 0);            // warp by res -> g_warped
    k_conv<<<g2, T>>>(x, res, Wc, bias, out);             // adj + src pass-through
    k_combine_f<<<gc, T, smem_cb>>>(res);                 // -> g_newres
    k_warpdown<<<gw, T>>>(nullptr, 1, out, 1);            // warp by new_res -> out[16..31]
}